// round 9
// baseline (speedup 1.0000x reference)
#include <cuda_runtime.h>
#include <cuda_bf16.h>
#include <math.h>
#include <stdint.h>

#define BB 64
#define TT 64
#define AA 64
#define HH 1024
#define CC 16

#define NT 128
#define KC 32
#define NGRP 40

#define KSPLIT 32
#define TAU_KB (HH / KSPLIT)   // 32

// smem layout (bytes, per buffer)
#define A_PL   5120            // 64 rows * 80 B
#define OFF_B  20480           // 4 A-planes (b0h,b0l,b1h,b1l)
#define B_PL   8704            // 32 rows * 272 B
#define BUF_SZ 37888
#define SMEM_SZ (2 * BUF_SZ)   // 75776

// Scratch (device globals; no runtime allocation)
__device__ __nv_bfloat16 g_a0h[BB * TT * AA], g_a0l[BB * TT * AA];
__device__ __nv_bfloat16 g_a1h[BB * TT * HH], g_a1l[BB * TT * HH];
__device__ __nv_bfloat16 g_a2h[BB * TT * HH], g_a2l[BB * TT * HH];
__device__ float g_tauc[BB * HH];
__device__ float g_tau[BB * HH];
__device__ float g_part[KSPLIT * BB * HH];
__device__ int   g_cat_cnt[CC];
__device__ int   g_cat_list[CC * BB];
__device__ int   g_grp_cat[NGRP], g_grp_b0[NGRP], g_grp_b1[NGRP], g_grp_nb[NGRP];

// ---------------- helpers ----------------
__device__ __forceinline__ uint32_t smem_u32(const void* p) {
    uint32_t a;
    asm("{ .reg .u64 t; cvta.to.shared.u64 t, %1; cvt.u32.u64 %0, t; }"
        : "=r"(a) : "l"(p));
    return a;
}
__device__ __forceinline__ void split_pair(float x, float y, uint32_t& h, uint32_t& l) {
    __nv_bfloat162 hb = __floats2bfloat162_rn(x, y);   // low 16 = x
    float hx = __bfloat162float(hb.x);
    float hy = __bfloat162float(hb.y);
    __nv_bfloat162 lb = __floats2bfloat162_rn(x - hx, y - hy);
    h = *reinterpret_cast<uint32_t*>(&hb);
    l = *reinterpret_cast<uint32_t*>(&lb);
}
__device__ __forceinline__ void mma_bf16(float* c, const uint32_t* a, uint32_t b0, uint32_t b1) {
    asm volatile(
        "mma.sync.aligned.m16n8k16.row.col.f32.bf16.bf16.f32 "
        "{%0,%1,%2,%3}, {%4,%5,%6,%7}, {%8,%9}, {%0,%1,%2,%3};"
        : "+f"(c[0]), "+f"(c[1]), "+f"(c[2]), "+f"(c[3])
        : "r"(a[0]), "r"(a[1]), "r"(a[2]), "r"(a[3]), "r"(b0), "r"(b1));
}
__device__ __forceinline__ void ldsm_x4(uint32_t* r, uint32_t addr) {
    asm volatile("ldmatrix.sync.aligned.m8n8.x4.shared.b16 {%0,%1,%2,%3}, [%4];"
                 : "=r"(r[0]), "=r"(r[1]), "=r"(r[2]), "=r"(r[3]) : "r"(addr));
}
__device__ __forceinline__ void ldsm_x4_t(uint32_t* r, uint32_t addr) {
    asm volatile("ldmatrix.sync.aligned.m8n8.x4.trans.shared.b16 {%0,%1,%2,%3}, [%4];"
                 : "=r"(r[0]), "=r"(r[1]), "=r"(r[2]), "=r"(r[3]) : "r"(addr));
}
__device__ __forceinline__ void cp_async16(uint32_t s, const void* g) {
    asm volatile("cp.async.ca.shared.global [%0], [%1], 16;" :: "r"(s), "l"(g));
}
#define CP_COMMIT() asm volatile("cp.async.commit_group;" ::: "memory")
#define CP_WAIT0()  asm volatile("cp.async.wait_group 0;" ::: "memory")

// ---------------------------------------------------------------------------
// prep: bucket batches by category + build work groups (<=2 batches/group)
// ---------------------------------------------------------------------------
__global__ void prep_kernel(const int* __restrict__ cat_ids) {
    if (threadIdx.x != 0) return;
    int g = 0;
    for (int c = 0; c < CC; ++c) {
        int cnt = 0;
        for (int b = 0; b < BB; ++b)
            if (cat_ids[b] == c) g_cat_list[c * BB + cnt++] = b;
        g_cat_cnt[c] = cnt;
        for (int i = 0; i < cnt; i += 2) {
            g_grp_cat[g] = c;
            g_grp_b0[g]  = g_cat_list[c * BB + i];
            g_grp_b1[g]  = (i + 1 < cnt) ? g_cat_list[c * BB + i + 1]
                                         : g_cat_list[c * BB + i];
            g_grp_nb[g]  = (i + 1 < cnt) ? 2 : 1;
            g++;
        }
    }
    for (; g < NGRP; ++g) g_grp_cat[g] = -1;
}

// ---------------------------------------------------------------------------
// actconv: actions fp32 -> bf16 hi/lo planes
// ---------------------------------------------------------------------------
__global__ void actconv_kernel(const float* __restrict__ actions) {
    int i = blockIdx.x * 512 + threadIdx.x;    // pair index
    float x = actions[2 * i], y = actions[2 * i + 1];
    uint32_t h, l;
    split_pair(x, y, h, l);
    ((uint32_t*)g_a0h)[i] = h;
    ((uint32_t*)g_a0l)[i] = l;
}

// ---------------------------------------------------------------------------
// tau1: per-batch sinusoidal embedding vector (1024)
// ---------------------------------------------------------------------------
__global__ void tau1_kernel(const int* __restrict__ timesteps) {
    const int b = blockIdx.x;
    const int tid = threadIdx.x;
    const float t = (float)timesteps[b];
    const int half = HH / 2;
    const float scale = logf(10000.0f) / (float)half;
    for (int d = tid; d < HH; d += 256) {
        int j = (d < half) ? d : (d - half);
        float f = t * expf(-(float)j * scale);
        g_tau[b * HH + d] = (d < half) ? sinf(f) : cosf(f);
    }
}

// ---------------------------------------------------------------------------
// tau2: cat-grouped, K-split matvec partials
// ---------------------------------------------------------------------------
__global__ void tau2_kernel(const float* __restrict__ W2) {
    const int cat = blockIdx.y;
    const int z   = blockIdx.z;
    const int tid = threadIdx.x;
    const int n2  = blockIdx.x * 128 + tid;
    const int cnt = g_cat_cnt[cat];
    if (cnt == 0) return;

    __shared__ float ts[8][TAU_KB];
    const int k0 = z * TAU_KB;
    const float* Wp = W2 + (size_t)cat * 2 * HH * HH
                         + (size_t)(HH + k0) * HH + 2 * n2;

    for (int base = 0; base < cnt; base += 8) {
        int nb = min(8, cnt - base);
        __syncthreads();
        for (int bl = 0; bl < nb; ++bl) {
            int bb = g_cat_list[cat * BB + base + bl];
            for (int d = tid; d < TAU_KB; d += 128)
                ts[bl][d] = g_tau[bb * HH + k0 + d];
        }
        __syncthreads();
        float2 acc[8];
        #pragma unroll
        for (int bl = 0; bl < 8; ++bl) acc[bl] = make_float2(0.f, 0.f);
        #pragma unroll 4
        for (int k = 0; k < TAU_KB; ++k) {
            float2 w = *(const float2*)&Wp[(size_t)k * HH];
            #pragma unroll
            for (int bl = 0; bl < 8; ++bl) {
                acc[bl].x = fmaf(ts[bl][k], w.x, acc[bl].x);
                acc[bl].y = fmaf(ts[bl][k], w.y, acc[bl].y);
            }
        }
        for (int bl = 0; bl < nb; ++bl) {
            int bb = g_cat_list[cat * BB + base + bl];
            *(float2*)&g_part[((size_t)z * BB + bb) * HH + 2 * n2] = acc[bl];
        }
    }
}

// ---------------------------------------------------------------------------
// tau3: deterministic reduce of partials + bias -> g_tauc
// ---------------------------------------------------------------------------
__global__ void tau3_kernel(const int* __restrict__ cat_ids,
                            const float* __restrict__ b2) {
    const int b = blockIdx.y;
    const int n = blockIdx.x * 256 + threadIdx.x;
    const int c = cat_ids[b];
    float s = b2[c * HH + n];
    #pragma unroll
    for (int z = 0; z < KSPLIT; ++z)
        s += g_part[((size_t)z * BB + b) * HH + n];
    g_tauc[b * HH + n] = s;
}

// ---------------------------------------------------------------------------
// Category-grouped split-bf16 mma layer. 512 threads, 16 warps (4m x 4n).
// Computes, for up to 2 batches of one category, a 64 x 128 output tile:
//   out[b] = act( A[b](64 x K) @ W[cat](K x 1024) + addend )
// A supplied as pre-split bf16 hi/lo planes; W converted in-loop (once per
// 2 batches). OUTMODE 0: fp32 out; OUTMODE 1: bf16 hi/lo planes.
// ---------------------------------------------------------------------------
template <int K, int ACT, int ADDMODE, int OUTMODE>
__global__ void __launch_bounds__(512, 1)
mma_layer(const __nv_bfloat16* __restrict__ Ahp,
          const __nv_bfloat16* __restrict__ Alp,
          const float* __restrict__ Wbase, size_t wstride,
          const float* __restrict__ addv,
          float* __restrict__ outf,
          __nv_bfloat16* __restrict__ outh,
          __nv_bfloat16* __restrict__ outl) {
    extern __shared__ char sm[];
    const int grp = blockIdx.y;
    const int cat = g_grp_cat[grp];
    if (cat < 0) return;
    const int b0 = g_grp_b0[grp];
    const int b1 = g_grp_b1[grp];
    const int nb = g_grp_nb[grp];
    const int nt  = blockIdx.x;
    const int tid = threadIdx.x;
    const int lane = tid & 31, warp = tid >> 5;
    const int wm = warp & 3, wn = warp >> 2;   // 4 x 4 warp grid
    const uint32_t smb = smem_u32(sm);

    const float* W = Wbase + (size_t)cat * wstride + nt * NT;
    const __nv_bfloat16* Aptr[4] = {
        Ahp + (size_t)b0 * 64 * K, Alp + (size_t)b0 * 64 * K,
        Ahp + (size_t)b1 * 64 * K, Alp + (size_t)b1 * 64 * K};

    float acc[2][4][4];
    #pragma unroll
    for (int i = 0; i < 2; ++i)
        #pragma unroll
        for (int j = 0; j < 4; ++j)
            #pragma unroll
            for (int q = 0; q < 4; ++q) acc[i][j][q] = 0.0f;

    constexpr int NCHUNK = K / KC;

    // A via cp.async: 1024 x 16B items, i = tid + 512r:
    //   pb = i>>8 (b0h,b0l,b1h,b1l), m = (i>>2)&63, kq = i&3
    auto issueA = [&](int k0, int buf) {
        #pragma unroll
        for (int r = 0; r < 2; ++r) {
            int i = tid + r * 512;
            int pb = i >> 8, m = (i >> 2) & 63, kq = i & 3;
            const __nv_bfloat16* gp = Aptr[pb] + (size_t)m * K + k0 + kq * 8;
            cp_async16(smb + buf * BUF_SZ + pb * A_PL + m * 80 + kq * 16, gp);
        }
    };
    // B: 1024 float4 items, i = tid + 512r: k = i>>5, n4 = i&31
    float4 pb4[2];
    auto loadB = [&](int k0) {
        #pragma unroll
        for (int r = 0; r < 2; ++r) {
            int i = tid + r * 512, k = i >> 5, n4 = i & 31;
            pb4[r] = *(const float4*)&W[(size_t)(k0 + k) * HH + n4 * 4];
        }
    };
    auto stsB = [&](int buf) {
        #pragma unroll
        for (int r = 0; r < 2; ++r) {
            int i = tid + r * 512, k = i >> 5, n4 = i & 31;
            float4 v = pb4[r];
            uint32_t h01, l01, h23, l23;
            split_pair(v.x, v.y, h01, l01);
            split_pair(v.z, v.w, h23, l23);
            char* base = sm + buf * BUF_SZ + OFF_B + k * 272 + n4 * 8;
            *(uint2*)(base)        = make_uint2(h01, h23);
            *(uint2*)(base + B_PL) = make_uint2(l01, l23);
        }
    };

    const int l15 = lane & 15, g16 = lane >> 4;

    // prologue: chunk 0 into buffer 0
    issueA(0, 0); CP_COMMIT();
    loadB(0);
    stsB(0);
    CP_WAIT0();
    __syncthreads();

    for (int ch = 0; ch < NCHUNK; ++ch) {
        const int cur = ch & 1;
        if (ch + 1 < NCHUNK) {
            issueA((ch + 1) * KC, cur ^ 1); CP_COMMIT();
            loadB((ch + 1) * KC);
        }

        // MMA on buffer cur
        {
            uint32_t abase = smb + cur * BUF_SZ;
            uint32_t bh = abase + OFF_B, bl = bh + B_PL;
            #pragma unroll
            for (int t = 0; t < 2; ++t) {
                uint32_t Bh[2][4], Bl[2][4];
                int kr = t * 16 + l15;
                #pragma unroll
                for (int nfp = 0; nfp < 2; ++nfp) {
                    uint32_t bb = kr * 272 + (wn * 32 + nfp * 16 + g16 * 8) * 2;
                    ldsm_x4_t(Bh[nfp], bh + bb);
                    ldsm_x4_t(Bl[nfp], bl + bb);
                }
                uint32_t abyte = (wm * 16 + l15) * 80 + t * 32 + g16 * 16;
                #pragma unroll
                for (int bt = 0; bt < 2; ++bt) {
                    uint32_t Ahf[4], Alf[4];
                    ldsm_x4(Ahf, abase + (bt * 2)     * A_PL + abyte);
                    ldsm_x4(Alf, abase + (bt * 2 + 1) * A_PL + abyte);
                    #pragma unroll
                    for (int nf = 0; nf < 4; ++nf) {
                        uint32_t bh0 = Bh[nf >> 1][(nf & 1) * 2];
                        uint32_t bh1 = Bh[nf >> 1][(nf & 1) * 2 + 1];
                        uint32_t bl0 = Bl[nf >> 1][(nf & 1) * 2];
                        uint32_t bl1 = Bl[nf >> 1][(nf & 1) * 2 + 1];
                        mma_bf16(acc[bt][nf], Ahf, bh0, bh1);   // hi*hi
                        mma_bf16(acc[bt][nf], Ahf, bl0, bl1);   // hi*lo
                        mma_bf16(acc[bt][nf], Alf, bh0, bh1);   // lo*hi
                    }
                }
            }
        }

        if (ch + 1 < NCHUNK) {
            stsB(cur ^ 1);   // B regs arrived during MMA
            CP_WAIT0();
        }
        __syncthreads();
    }

    // ---- epilogue ----
    const int lr = lane >> 2, lc = lane & 3;
    const int bs[2] = {b0, b1};
    for (int bt = 0; bt < nb; ++bt) {
        const int b = bs[bt];
        const float* addp = (ADDMODE == 0) ? (addv + (size_t)cat * HH)
                                           : (addv + (size_t)b * HH);
        const int r0 = wm * 16 + lr;
        #pragma unroll
        for (int nf = 0; nf < 4; ++nf) {
            int ncol = nt * NT + wn * 32 + nf * 8 + lc * 2;
            float bv0 = addp[ncol], bv1 = addp[ncol + 1];
            float v0 = acc[bt][nf][0] + bv0;
            float v1 = acc[bt][nf][1] + bv1;
            float v2 = acc[bt][nf][2] + bv0;
            float v3 = acc[bt][nf][3] + bv1;
            if (ACT == 1) {
                v0 = v0 / (1.0f + expf(-v0));
                v1 = v1 / (1.0f + expf(-v1));
                v2 = v2 / (1.0f + expf(-v2));
                v3 = v3 / (1.0f + expf(-v3));
            }
            size_t o0 = ((size_t)b * TT + r0)     * HH + ncol;
            size_t o1 = ((size_t)b * TT + r0 + 8) * HH + ncol;
            if (OUTMODE == 0) {
                *(float2*)&outf[o0] = make_float2(v0, v1);
                *(float2*)&outf[o1] = make_float2(v2, v3);
            } else {
                uint32_t h, l;
                split_pair(v0, v1, h, l);
                *(uint32_t*)&outh[o0] = h;
                *(uint32_t*)&outl[o0] = l;
                split_pair(v2, v3, h, l);
                *(uint32_t*)&outh[o1] = h;
                *(uint32_t*)&outl[o1] = l;
            }
        }
    }
}

extern "C" void kernel_launch(void* const* d_in, const int* in_sizes, int n_in,
                              void* d_out, int out_size) {
    const float* actions   = (const float*)d_in[0];
    const int*   timesteps = (const int*)d_in[1];
    const int*   cat_ids   = (const int*)d_in[2];
    const float* W1 = (const float*)d_in[3];
    const float* b1 = (const float*)d_in[4];
    const float* W2 = (const float*)d_in[5];
    const float* b2 = (const float*)d_in[6];
    const float* W3 = (const float*)d_in[7];
    const float* b3 = (const float*)d_in[8];
    float* out = (float*)d_out;

    __nv_bfloat16 *a0h, *a0l, *a1h, *a1l, *a2h, *a2l;
    float *tauc;
    cudaGetSymbolAddress((void**)&a0h, g_a0h);
    cudaGetSymbolAddress((void**)&a0l, g_a0l);
    cudaGetSymbolAddress((void**)&a1h, g_a1h);
    cudaGetSymbolAddress((void**)&a1l, g_a1l);
    cudaGetSymbolAddress((void**)&a2h, g_a2h);
    cudaGetSymbolAddress((void**)&a2l, g_a2l);
    cudaGetSymbolAddress((void**)&tauc, g_tauc);

    cudaFuncSetAttribute(mma_layer<AA, 0, 0, 1>,
                         cudaFuncAttributeMaxDynamicSharedMemorySize, SMEM_SZ);
    cudaFuncSetAttribute(mma_layer<HH, 1, 1, 1>,
                         cudaFuncAttributeMaxDynamicSharedMemorySize, SMEM_SZ);
    cudaFuncSetAttribute(mma_layer<HH, 0, 0, 0>,
                         cudaFuncAttributeMaxDynamicSharedMemorySize, SMEM_SZ);

    prep_kernel<<<1, 32>>>(cat_ids);
    tau1_kernel<<<BB, 256>>>(timesteps);
    actconv_kernel<<<BB * TT * AA / 1024, 512>>>(actions);

    // layer 1: aemb planes = actions @ W1 + b1
    mma_layer<AA, 0, 0, 1><<<dim3(HH / NT, NGRP), 512, SMEM_SZ>>>(
        a0h, a0l, W1, (size_t)AA * HH, b1, nullptr, a1h, a1l);

    // tau matvec
    tau2_kernel<<<dim3(HH / 2 / 128, CC, KSPLIT), 128>>>(W2);
    tau3_kernel<<<dim3(HH / 256, BB), 256>>>(cat_ids, b2);

    // layer 2: h planes = swish(aemb @ W2[:1024] + tauc)
    mma_layer<HH, 1, 1, 1><<<dim3(HH / NT, NGRP), 512, SMEM_SZ>>>(
        a1h, a1l, W2, (size_t)2 * HH * HH, tauc, nullptr, a2h, a2l);

    // layer 3: out fp32 = h @ W3 + b3
    mma_layer<HH, 0, 0, 0><<<dim3(HH / NT, NGRP), 512, SMEM_SZ>>>(
        a2h, a2l, W3, (size_t)HH * HH, b3, out, nullptr, nullptr);
}

// round 12
// speedup vs baseline: 1.4524x; 1.4524x over previous
#include <cuda_runtime.h>
#include <cuda_bf16.h>
#include <math.h>
#include <stdint.h>

#define BB 64
#define TT 64
#define AA 64
#define HH 1024
#define CC 16

#define NT 128     // N cols per CTA
#define KC 32      // K floats per chunk

#define KSPLIT 32
#define TAU_KB (HH / KSPLIT)   // 32

// Scratch (device globals; no runtime allocation)
__device__ __align__(16) __nv_bfloat16 g_a0h[BB * TT * AA], g_a0l[BB * TT * AA];
__device__ __align__(16) __nv_bfloat16 g_a1h[BB * TT * HH], g_a1l[BB * TT * HH];
__device__ __align__(16) __nv_bfloat16 g_a2h[BB * TT * HH], g_a2l[BB * TT * HH];
__device__ float g_tauc[BB * HH];
__device__ float g_tau[BB * HH];
__device__ float g_part[KSPLIT * BB * HH];
__device__ int   g_cat_cnt[CC];
__device__ int   g_cat_list[CC * BB];

// ---------------- helpers ----------------
__device__ __forceinline__ uint32_t smem_u32(const void* p) {
    uint32_t a;
    asm("{ .reg .u64 t; cvta.to.shared.u64 t, %1; cvt.u32.u64 %0, t; }"
        : "=r"(a) : "l"(p));
    return a;
}
__device__ __forceinline__ void split_pair(float x, float y, uint32_t& h, uint32_t& l) {
    __nv_bfloat162 hb = __floats2bfloat162_rn(x, y);   // low 16 = x
    float hx = __bfloat162float(hb.x);
    float hy = __bfloat162float(hb.y);
    __nv_bfloat162 lb = __floats2bfloat162_rn(x - hx, y - hy);
    h = *reinterpret_cast<uint32_t*>(&hb);
    l = *reinterpret_cast<uint32_t*>(&lb);
}
__device__ __forceinline__ void mma_bf16(float* c, const uint32_t* a, uint32_t b0, uint32_t b1) {
    asm volatile(
        "mma.sync.aligned.m16n8k16.row.col.f32.bf16.bf16.f32 "
        "{%0,%1,%2,%3}, {%4,%5,%6,%7}, {%8,%9}, {%0,%1,%2,%3};"
        : "+f"(c[0]), "+f"(c[1]), "+f"(c[2]), "+f"(c[3])
        : "r"(a[0]), "r"(a[1]), "r"(a[2]), "r"(a[3]), "r"(b0), "r"(b1));
}
__device__ __forceinline__ void ldsm_x4(uint32_t* r, uint32_t addr) {
    asm volatile("ldmatrix.sync.aligned.m8n8.x4.shared.b16 {%0,%1,%2,%3}, [%4];"
                 : "=r"(r[0]), "=r"(r[1]), "=r"(r[2]), "=r"(r[3]) : "r"(addr));
}
__device__ __forceinline__ void ldsm_x4_t(uint32_t* r, uint32_t addr) {
    asm volatile("ldmatrix.sync.aligned.m8n8.x4.trans.shared.b16 {%0,%1,%2,%3}, [%4];"
                 : "=r"(r[0]), "=r"(r[1]), "=r"(r[2]), "=r"(r[3]) : "r"(addr));
}

// ---------------------------------------------------------------------------
// prep: bucket batches by category (for tau2)
// ---------------------------------------------------------------------------
__global__ void prep_kernel(const int* __restrict__ cat_ids) {
    int c = threadIdx.x;
    if (c >= CC) return;
    int cnt = 0;
    for (int b = 0; b < BB; ++b)
        if (cat_ids[b] == c) g_cat_list[c * BB + cnt++] = b;
    g_cat_cnt[c] = cnt;
}

// ---------------------------------------------------------------------------
// actconv: actions fp32 -> bf16 hi/lo planes
// ---------------------------------------------------------------------------
__global__ void actconv_kernel(const float* __restrict__ actions) {
    int i = blockIdx.x * 512 + threadIdx.x;    // pair index
    float x = actions[2 * i], y = actions[2 * i + 1];
    uint32_t h, l;
    split_pair(x, y, h, l);
    ((uint32_t*)g_a0h)[i] = h;
    ((uint32_t*)g_a0l)[i] = l;
}

// ---------------------------------------------------------------------------
// tau1: per-batch sinusoidal embedding vector (1024)
// ---------------------------------------------------------------------------
__global__ void tau1_kernel(const int* __restrict__ timesteps) {
    const int b = blockIdx.x;
    const int tid = threadIdx.x;
    const float t = (float)timesteps[b];
    const int half = HH / 2;
    const float scale = logf(10000.0f) / (float)half;
    for (int d = tid; d < HH; d += 256) {
        int j = (d < half) ? d : (d - half);
        float f = t * expf(-(float)j * scale);
        g_tau[b * HH + d] = (d < half) ? sinf(f) : cosf(f);
    }
}

// ---------------------------------------------------------------------------
// tau2: cat-grouped, K-split matvec partials
// grid(HH/2/128, CC, KSPLIT), 128 threads, float2 loads.
// ---------------------------------------------------------------------------
__global__ void tau2_kernel(const float* __restrict__ W2) {
    const int cat = blockIdx.y;
    const int z   = blockIdx.z;
    const int tid = threadIdx.x;
    const int n2  = blockIdx.x * 128 + tid;
    const int cnt = g_cat_cnt[cat];
    if (cnt == 0) return;

    __shared__ float ts[8][TAU_KB];
    const int k0 = z * TAU_KB;
    const float* Wp = W2 + (size_t)cat * 2 * HH * HH
                         + (size_t)(HH + k0) * HH + 2 * n2;

    for (int base = 0; base < cnt; base += 8) {
        int nb = min(8, cnt - base);
        __syncthreads();
        for (int bl = 0; bl < nb; ++bl) {
            int bb = g_cat_list[cat * BB + base + bl];
            for (int d = tid; d < TAU_KB; d += 128)
                ts[bl][d] = g_tau[bb * HH + k0 + d];
        }
        __syncthreads();
        float2 acc[8];
        #pragma unroll
        for (int bl = 0; bl < 8; ++bl) acc[bl] = make_float2(0.f, 0.f);
        #pragma unroll 4
        for (int k = 0; k < TAU_KB; ++k) {
            float2 w = *(const float2*)&Wp[(size_t)k * HH];
            #pragma unroll
            for (int bl = 0; bl < 8; ++bl) {
                acc[bl].x = fmaf(ts[bl][k], w.x, acc[bl].x);
                acc[bl].y = fmaf(ts[bl][k], w.y, acc[bl].y);
            }
        }
        for (int bl = 0; bl < nb; ++bl) {
            int bb = g_cat_list[cat * BB + base + bl];
            *(float2*)&g_part[((size_t)z * BB + bb) * HH + 2 * n2] = acc[bl];
        }
    }
}

// ---------------------------------------------------------------------------
// tau3: deterministic reduce of partials + bias -> g_tauc
// ---------------------------------------------------------------------------
__global__ void tau3_kernel(const int* __restrict__ cat_ids,
                            const float* __restrict__ b2) {
    const int b = blockIdx.y;
    const int n = blockIdx.x * 256 + threadIdx.x;
    const int c = cat_ids[b];
    float s = b2[c * HH + n];
    #pragma unroll
    for (int z = 0; z < KSPLIT; ++z)
        s += g_part[((size_t)z * BB + b) * HH + n];
    g_tauc[b * HH + n] = s;
}

// ---------------------------------------------------------------------------
// Split-bf16 mma.sync GEMM layer (R8-proven single-buffer pipeline).
// A supplied as pre-split bf16 hi/lo planes (pure copy into smem);
// B fp32 -> bf16 hi/lo converted in-loop from register prefetch.
// grid(HH/NT, BB), 256 threads (2m x 4n warps, 32x32 each).
//   out[b] = act( A[b](64 x K) @ W[cat[b]](K x 1024) + addend )
// OUTMODE 0: fp32 out; OUTMODE 1: bf16 hi/lo planes.
// ---------------------------------------------------------------------------
template <int K, int ACT, int ADDMODE, int OUTMODE>
__global__ void __launch_bounds__(256, 2)
mma_layer(const __nv_bfloat16* __restrict__ Ahp,
          const __nv_bfloat16* __restrict__ Alp,
          const float* __restrict__ Wbase, size_t wstride,
          const float* __restrict__ addv,
          const int* __restrict__ cat_ids,
          float* __restrict__ outf,
          __nv_bfloat16* __restrict__ outh,
          __nv_bfloat16* __restrict__ outl) {
    // A planes: bf16 [m=64][k=32], row stride 20 words (80 B)
    __shared__ __align__(16) uint32_t As_hi[64 * 20];
    __shared__ __align__(16) uint32_t As_lo[64 * 20];
    // B planes: bf16 [k=32][n=128], row stride 68 words (272 B)
    __shared__ __align__(16) uint32_t Bs_hi[32 * 68];
    __shared__ __align__(16) uint32_t Bs_lo[32 * 68];

    const int tid  = threadIdx.x;
    const int lane = tid & 31;
    const int warp = tid >> 5;
    const int wm   = warp >> 2;   // 0..1
    const int wn   = warp & 3;    // 0..3
    const int b    = blockIdx.y;
    const int nt   = blockIdx.x;
    const int c    = cat_ids[b];

    const float* W = Wbase + (size_t)c * wstride + nt * NT;
    const __nv_bfloat16* Ah = Ahp + (size_t)b * 64 * K;
    const __nv_bfloat16* Al = Alp + (size_t)b * 64 * K;

    const uint32_t sAh = smem_u32(As_hi), sAl = smem_u32(As_lo);
    const uint32_t sBh = smem_u32(Bs_hi), sBl = smem_u32(Bs_lo);

    float acc[2][4][4];
    #pragma unroll
    for (int i = 0; i < 2; ++i)
        #pragma unroll
        for (int j = 0; j < 4; ++j)
            #pragma unroll
            for (int q = 0; q < 4; ++q) acc[i][j][q] = 0.0f;

    constexpr int NCHUNK = K / KC;

    // A: one 16B item per plane per thread: m = tid>>2, kq = tid&3
    const int a_m  = tid >> 2;
    const int a_kq = tid & 3;
    // B: 512 float4 items/chunk, i = tid + 256r: kp = i>>5 (k-pair), nq = i&31
    uint4 pah, pal;
    float4 pb0[2], pb1[2];

    // prefetch chunk 0
    pah = *(const uint4*)&Ah[(size_t)a_m * K + a_kq * 8];
    pal = *(const uint4*)&Al[(size_t)a_m * K + a_kq * 8];
    #pragma unroll
    for (int r = 0; r < 2; ++r) {
        int i = tid + r * 256, nq = i & 31, kp = i >> 5;
        pb0[r] = *(const float4*)&W[(size_t)(kp * 2)     * HH + nq * 4];
        pb1[r] = *(const float4*)&W[(size_t)(kp * 2 + 1) * HH + nq * 4];
    }

    const int l15 = lane & 15, g16 = lane >> 4;

    for (int ch = 0; ch < NCHUNK; ++ch) {
        __syncthreads();   // previous iteration's frag reads complete

        // ---- STS A (pure copy) ----
        *(uint4*)&As_hi[a_m * 20 + a_kq * 4] = pah;
        *(uint4*)&As_lo[a_m * 20 + a_kq * 4] = pal;
        // ---- STS B (convert fp32 -> bf16 hi/lo) ----
        #pragma unroll
        for (int r = 0; r < 2; ++r) {
            int i = tid + r * 256, nq = i & 31, kp = i >> 5;
            float4 v0 = pb0[r], v1 = pb1[r];
            uint32_t h01, l01, h23, l23;
            split_pair(v0.x, v0.y, h01, l01);
            split_pair(v0.z, v0.w, h23, l23);
            int idx0 = (kp * 2) * 68 + nq * 2;
            *(uint2*)&Bs_hi[idx0] = make_uint2(h01, h23);
            *(uint2*)&Bs_lo[idx0] = make_uint2(l01, l23);
            split_pair(v1.x, v1.y, h01, l01);
            split_pair(v1.z, v1.w, h23, l23);
            int idx1 = (kp * 2 + 1) * 68 + nq * 2;
            *(uint2*)&Bs_hi[idx1] = make_uint2(h01, h23);
            *(uint2*)&Bs_lo[idx1] = make_uint2(l01, l23);
        }
        __syncthreads();

        // ---- prefetch next chunk (overlaps MMA below) ----
        if (ch + 1 < NCHUNK) {
            int k0 = (ch + 1) * KC;
            pah = *(const uint4*)&Ah[(size_t)a_m * K + k0 + a_kq * 8];
            pal = *(const uint4*)&Al[(size_t)a_m * K + k0 + a_kq * 8];
            #pragma unroll
            for (int r = 0; r < 2; ++r) {
                int i = tid + r * 256, nq = i & 31, kp = i >> 5;
                pb0[r] = *(const float4*)&W[(size_t)(k0 + kp * 2)     * HH + nq * 4];
                pb1[r] = *(const float4*)&W[(size_t)(k0 + kp * 2 + 1) * HH + nq * 4];
            }
        }

        // ---- MMA phase: two k16 steps, ldmatrix frags ----
        #pragma unroll
        for (int t = 0; t < 2; ++t) {
            uint32_t Ahf[2][4], Alf[2][4];
            #pragma unroll
            for (int ms = 0; ms < 2; ++ms) {
                uint32_t abyte = (wm * 32 + ms * 16 + l15) * 80 + t * 32 + g16 * 16;
                ldsm_x4(Ahf[ms], sAh + abyte);
                ldsm_x4(Alf[ms], sAl + abyte);
            }
            uint32_t Bh[2][4], Bl[2][4];
            #pragma unroll
            for (int nfp = 0; nfp < 2; ++nfp) {
                int kr = t * 16 + l15;
                uint32_t bbyte = kr * 272 + (wn * 32 + nfp * 16 + g16 * 8) * 2;
                ldsm_x4_t(Bh[nfp], sBh + bbyte);
                ldsm_x4_t(Bl[nfp], sBl + bbyte);
            }
            #pragma unroll
            for (int nf = 0; nf < 4; ++nf) {
                uint32_t bh0 = Bh[nf >> 1][(nf & 1) * 2];
                uint32_t bh1 = Bh[nf >> 1][(nf & 1) * 2 + 1];
                uint32_t bl0 = Bl[nf >> 1][(nf & 1) * 2];
                uint32_t bl1 = Bl[nf >> 1][(nf & 1) * 2 + 1];
                #pragma unroll
                for (int ms = 0; ms < 2; ++ms) {
                    mma_bf16(acc[ms][nf], Ahf[ms], bh0, bh1);   // hi*hi
                    mma_bf16(acc[ms][nf], Ahf[ms], bl0, bl1);   // hi*lo
                    mma_bf16(acc[ms][nf], Alf[ms], bh0, bh1);   // lo*hi
                }
            }
        }
    }

    // ---- epilogue ----
    const float* addp = (ADDMODE == 0) ? (addv + (size_t)c * HH)
                                       : (addv + (size_t)b * HH);
    const int lr = lane >> 2;
    const int lc = lane & 3;
    #pragma unroll
    for (int ms = 0; ms < 2; ++ms) {
        int r0 = wm * 32 + ms * 16 + lr;
        #pragma unroll
        for (int nf = 0; nf < 4; ++nf) {
            int ncol = nt * NT + wn * 32 + nf * 8 + lc * 2;
            float bv0 = addp[ncol], bv1 = addp[ncol + 1];
            float v0 = acc[ms][nf][0] + bv0;
            float v1 = acc[ms][nf][1] + bv1;
            float v2 = acc[ms][nf][2] + bv0;
            float v3 = acc[ms][nf][3] + bv1;
            if (ACT == 1) {
                v0 = v0 / (1.0f + expf(-v0));
                v1 = v1 / (1.0f + expf(-v1));
                v2 = v2 / (1.0f + expf(-v2));
                v3 = v3 / (1.0f + expf(-v3));
            }
            size_t o0 = ((size_t)b * TT + r0)     * HH + ncol;
            size_t o1 = ((size_t)b * TT + r0 + 8) * HH + ncol;
            if (OUTMODE == 0) {
                *(float2*)&outf[o0] = make_float2(v0, v1);
                *(float2*)&outf[o1] = make_float2(v2, v3);
            } else {
                uint32_t h, l;
                split_pair(v0, v1, h, l);
                *(uint32_t*)&outh[o0] = h;
                *(uint32_t*)&outl[o0] = l;
                split_pair(v2, v3, h, l);
                *(uint32_t*)&outh[o1] = h;
                *(uint32_t*)&outl[o1] = l;
            }
        }
    }
}

extern "C" void kernel_launch(void* const* d_in, const int* in_sizes, int n_in,
                              void* d_out, int out_size) {
    const float* actions   = (const float*)d_in[0];
    const int*   timesteps = (const int*)d_in[1];
    const int*   cat_ids   = (const int*)d_in[2];
    const float* W1 = (const float*)d_in[3];
    const float* b1 = (const float*)d_in[4];
    const float* W2 = (const float*)d_in[5];
    const float* b2 = (const float*)d_in[6];
    const float* W3 = (const float*)d_in[7];
    const float* b3 = (const float*)d_in[8];
    float* out = (float*)d_out;

    __nv_bfloat16 *a0h, *a0l, *a1h, *a1l, *a2h, *a2l;
    float *tauc;
    cudaGetSymbolAddress((void**)&a0h, g_a0h);
    cudaGetSymbolAddress((void**)&a0l, g_a0l);
    cudaGetSymbolAddress((void**)&a1h, g_a1h);
    cudaGetSymbolAddress((void**)&a1l, g_a1l);
    cudaGetSymbolAddress((void**)&a2h, g_a2h);
    cudaGetSymbolAddress((void**)&a2l, g_a2l);
    cudaGetSymbolAddress((void**)&tauc, g_tauc);

    prep_kernel<<<1, CC>>>(cat_ids);
    tau1_kernel<<<BB, 256>>>(timesteps);
    actconv_kernel<<<BB * TT * AA / 1024, 512>>>(actions);

    // layer 1: aemb planes = actions @ W1 + b1
    mma_layer<AA, 0, 0, 1><<<dim3(HH / NT, BB), 256>>>(
        a0h, a0l, W1, (size_t)AA * HH, b1, cat_ids, nullptr, a1h, a1l);

    // tau matvec: K-split partials + deterministic reduce
    tau2_kernel<<<dim3(HH / 2 / 128, CC, KSPLIT), 128>>>(W2);
    tau3_kernel<<<dim3(HH / 256, BB), 256>>>(cat_ids, b2);

    // layer 2: h planes = swish(aemb @ W2[:1024] + tauc)
    mma_layer<HH, 1, 1, 1><<<dim3(HH / NT, BB), 256>>>(
        a1h, a1l, W2, (size_t)2 * HH * HH, tauc, cat_ids, nullptr, a2h, a2l);

    // layer 3: out fp32 = h @ W3 + b3
    mma_layer<HH, 0, 0, 0><<<dim3(HH / NT, BB), 256>>>(
        a2h, a2l, W3, (size_t)HH * HH, b3, cat_ids, out, nullptr, nullptr);
}